// round 7
// baseline (speedup 1.0000x reference)
#include <cuda_runtime.h>
#include <cuda_bf16.h>
#include <math.h>
#include <stdint.h>

#define DX 512
#define DU 256
#define DOUT 256
#define DK 768
#define NB 16
#define SEQL 4096
#define CW 64          // warmup length
#define NCH 74         // chunks
#define CTS 56         // chunk length (74*56 = 4144 >= 4096)
#define OUT_ELEMS (NB*SEQL*DOUT)           /* 16777216 */
#define ST_ELEMS  ((size_t)NB*(SEQL+1)*DX) /* 33562624 */

// ---------------- device scratch (static; no runtime allocation) ----------------
__device__ float g_M0[DK*DK];
__device__ float g_M1[DK*DK];
__device__ float g_Xa[DX*DX];
__device__ float g_Xb[DX*DX];
__device__ float g_P[DX*DX];
__device__ float g_T1[DX*DX];
__device__ float g_Amat[DX*DX];
__device__ float g_Apack[DX*DX];
__device__ float g_Bm[DX*DU];
__device__ float g_E[DOUT*DK];
__device__ float g_Bu[(size_t)NB*SEQL*DX];
__device__ float g_states_fallback[(size_t)NB*(SEQL+1)*DX];
__device__ float g_scale;
__device__ float g_kscale;
__device__ double g_logacc;

// bf16 split buffers. A-side layout [h,l,h]; B-side layout [h,h,l].
__device__ __nv_bfloat16 c_big1[(size_t)65536*1536]; // states3 (A-side)
__device__ __nv_bfloat16 c_big2[(size_t)65536*768];  // u3 (A-side)
__device__ __nv_bfloat16 c_kt[DK*2304];              // A-side DK
__device__ __nv_bfloat16 c_m [DK*2304];              // B-side DK
__device__ __nv_bfloat16 c_s [DX*1536];
__device__ __nv_bfloat16 c_st[DX*1536];
__device__ __nv_bfloat16 c_w1[DX*1536];
__device__ __nv_bfloat16 c_w2[DX*1536];
__device__ __nv_bfloat16 c_w3[DX*1536];
__device__ __nv_bfloat16 c_w4[DX*1536];
__device__ __nv_bfloat16 c_bm[DX*768];
__device__ __nv_bfloat16 c_dw[DOUT*768];

// ---------------- small kernels ----------------
__global__ void init_kernel() {
    int idx = blockIdx.x * blockDim.x + threadIdx.x;
    if (idx == 0) g_logacc = 0.0;
    if (idx < DX*DX) {
        int i = idx / DX, j = idx - i*DX;
        g_Xa[idx] = (i == j) ? 1.f : 0.f;
    }
}

__global__ void trace_kernel(const float* __restrict__ M, double w) {
    __shared__ float red[256];
    int tid = threadIdx.x;
    float s = 0.f;
    for (int i = tid; i < DK; i += 256) s += M[(size_t)i*DK + i];
    red[tid] = s; __syncthreads();
    for (int o = 128; o > 0; o >>= 1) {
        if (tid < o) red[tid] += red[tid+o];
        __syncthreads();
    }
    if (tid == 0) {
        float t = red[0];
        g_scale = 1.f / (t * t);
        g_logacc += w * log((double)t);
    }
}

__global__ void finalize_kernel() {
    double L = g_logacc;               // log(sigma^2)
    float sigma = (float)exp(0.5 * L);
    if (sigma < 1e-5f) sigma = 1e-5f;
    g_kscale = 1.f / (sigma + 0.002f);
}

__global__ void pack_kernel() {
    int idx = blockIdx.x * blockDim.x + threadIdx.x;   // DX*DX
    int n = idx >> 9, h = idx & 511;
    g_Apack[(h >> 2) * (DX*4) + n*4 + (h & 3)] = g_Amat[(size_t)n*DX + h];
}

__global__ void dcopy_kernel(const float* __restrict__ Kraw) {
    int idx = blockIdx.x * blockDim.x + threadIdx.x;   // DOUT*DU
    int o = idx >> 8, h = idx & 255;
    g_E[(size_t)o*DK + DX + h] = g_kscale * Kraw[(size_t)(DX+o)*DK + DX + h];
}

__global__ void state0_kernel(const float* __restrict__ st, float* __restrict__ states) {
    int idx = blockIdx.x * blockDim.x + threadIdx.x;   // NB*DX
    int b = idx >> 9, n = idx & 511;
    states[(size_t)b*(SEQL+1)*DX + n] = st[idx];
}

// ---------------- fp32 -> bf16 3-term split, generic gather ----------------
// bmode=0 (A-operand): dst row = [hi | lo | hi]
// bmode=1 (B-operand): dst row = [hi | hi | lo]
// So A3 . B3 over K3 = Ah.Bh + Al.Bh + Ah.Bl  (lo*lo term dropped, ~2^-32)
__global__ void split3_kernel(const float* __restrict__ src, __nv_bfloat16* __restrict__ dst,
                              long long rs, long long cs, int K, long long total,
                              int rpb, long long bstr, int bmode)
{
    long long idx = (long long)blockIdx.x * 256 + threadIdx.x;
    if (idx >= total) return;
    long long r = idx / K;
    int k = (int)(idx - r * K);
    long long so;
    if (rpb > 0) { long long b = r / rpb, rr = r - b*rpb; so = b*bstr + rr*rs + (long long)k*cs; }
    else so = r*rs + (long long)k*cs;
    float x = src[so];
    __nv_bfloat16 h = __float2bfloat16(x);
    __nv_bfloat16 l = __float2bfloat16(x - __bfloat162float(h));
    __nv_bfloat16* d = dst + r*(3LL*K);
    if (bmode) { d[k] = h; d[K+k] = h; d[2*K+k] = l; }
    else       { d[k] = h; d[K+k] = l; d[2*K+k] = h; }
}

// ---------------- tensor-core bf16-split GEMM ----------------
// C[M,N] = mult * (A3[M,K3] @ B3[N,K3]^T) + beta * Dm
// BM=BN=128, BK=64; 8 warps (2 M x 4 N), each warp 64x32; m16n8k16 HMMA.
__device__ __forceinline__ void cpa16(uint32_t s, const void* g) {
    asm volatile("cp.async.cg.shared.global [%0], [%1], 16;" :: "r"(s), "l"(g));
}
__device__ __forceinline__ void ldm4(uint32_t* f, uint32_t addr) {
    asm volatile("ldmatrix.sync.aligned.m8n8.x4.shared.b16 {%0,%1,%2,%3}, [%4];"
                 : "=r"(f[0]), "=r"(f[1]), "=r"(f[2]), "=r"(f[3]) : "r"(addr));
}
__device__ __forceinline__ void mma16816(float* c, const uint32_t* a, uint32_t b0, uint32_t b1) {
    asm volatile("mma.sync.aligned.m16n8k16.row.col.f32.bf16.bf16.f32 "
                 "{%0,%1,%2,%3}, {%4,%5,%6,%7}, {%8,%9}, {%0,%1,%2,%3};"
                 : "+f"(c[0]), "+f"(c[1]), "+f"(c[2]), "+f"(c[3])
                 : "r"(a[0]), "r"(a[1]), "r"(a[2]), "r"(a[3]), "r"(b0), "r"(b1));
}

__global__ __launch_bounds__(256)
void tc_gemm(const __nv_bfloat16* __restrict__ A3, const __nv_bfloat16* __restrict__ B3,
             const float* __restrict__ Dm, float* __restrict__ C,
             int M, int N, int K3, int ldd, int ldc,
             int amode, float alpha, float beta)
{
    extern __shared__ char smem[];
    const uint32_t ABUF = 16384;
    uint32_t sbase = (uint32_t)__cvta_generic_to_shared(smem);
    uint32_t sA = sbase;
    uint32_t sB = sbase + 2*ABUF;

    int tid = threadIdx.x;
    int wid = tid >> 5, lane = tid & 31;
    int wm = wid & 1, wn = wid >> 1;
    int m0 = blockIdx.y * 128, n0 = blockIdx.x * 128;

    // global->smem load mapping: row = tid>>1 (0..127), 4x16B per thread
    int lrow = tid >> 1;
    int ljb = (tid & 1) * 4;
    const __nv_bfloat16* gA = A3 + (size_t)(m0 + lrow) * K3;
    const __nv_bfloat16* gB = B3 + (size_t)(n0 + lrow) * K3;
    uint32_t srowA = sA + lrow*128;
    uint32_t srowB = sB + lrow*128;
    uint32_t rx = (lrow & 7) * 16;   // swizzle xor

    // ldmatrix per-lane addressing
    int q = lane >> 3, r = lane & 7;
    uint32_t aRow[4], aXor[4];
    #pragma unroll
    for (int mt = 0; mt < 4; ++mt) {
        int row = wm*64 + mt*16 + (q & 1)*8 + r;
        aRow[mt] = (uint32_t)row * 128;
        aXor[mt] = (uint32_t)(row & 7) * 16;
    }
    uint32_t aCsel = (uint32_t)(q >> 1) * 16;
    uint32_t bRow[2], bXor[2];
    #pragma unroll
    for (int p = 0; p < 2; ++p) {
        int row = wn*32 + (2*p + (q >> 1))*8 + r;
        bRow[p] = (uint32_t)row * 128;
        bXor[p] = (uint32_t)(row & 7) * 16;
    }
    uint32_t bCsel = (uint32_t)(q & 1) * 16;

    float acc[4][4][4];
    #pragma unroll
    for (int i = 0; i < 4; ++i)
        #pragma unroll
        for (int j = 0; j < 4; ++j)
            #pragma unroll
            for (int v = 0; v < 4; ++v) acc[i][j][v] = 0.f;

    int nk = K3 >> 6;

    // prologue: load buf 0
    #pragma unroll
    for (int i = 0; i < 4; ++i) {
        int j = ljb + i;
        cpa16(srowA + ((uint32_t)(j*16) ^ rx), gA + j*8);
        cpa16(srowB + ((uint32_t)(j*16) ^ rx), gB + j*8);
    }
    asm volatile("cp.async.commit_group;" ::: "memory");

    for (int ki = 0; ki < nk; ++ki) {
        uint32_t boff = (uint32_t)(ki & 1) * ABUF;
        bool more = (ki + 1 < nk);
        if (more) {
            uint32_t nboff = (uint32_t)((ki + 1) & 1) * ABUF;
            int kt = (ki + 1) << 6;
            #pragma unroll
            for (int i = 0; i < 4; ++i) {
                int j = ljb + i;
                cpa16(srowA + nboff + ((uint32_t)(j*16) ^ rx), gA + kt + j*8);
                cpa16(srowB + nboff + ((uint32_t)(j*16) ^ rx), gB + kt + j*8);
            }
            asm volatile("cp.async.commit_group;" ::: "memory");
            asm volatile("cp.async.wait_group 1;" ::: "memory");
        } else {
            asm volatile("cp.async.wait_group 0;" ::: "memory");
        }
        __syncthreads();

        #pragma unroll
        for (int kk = 0; kk < 4; ++kk) {
            uint32_t afr[4][4];
            #pragma unroll
            for (int mt = 0; mt < 4; ++mt)
                ldm4(afr[mt], sA + boff + aRow[mt] + (((uint32_t)(kk*32) + aCsel) ^ aXor[mt]));
            uint32_t bfr[2][4];
            #pragma unroll
            for (int p = 0; p < 2; ++p)
                ldm4(bfr[p], sB + boff + bRow[p] + (((uint32_t)(kk*32) + bCsel) ^ bXor[p]));
            #pragma unroll
            for (int mt = 0; mt < 4; ++mt)
                #pragma unroll
                for (int nt = 0; nt < 4; ++nt)
                    mma16816(acc[mt][nt], afr[mt], bfr[nt >> 1][(nt & 1)*2], bfr[nt >> 1][(nt & 1)*2 + 1]);
        }
        __syncthreads();
    }

    float mult = alpha;
    if (amode == 1) mult *= g_scale;
    else if (amode == 2) mult *= g_kscale;

    int cr = lane >> 2, cc = (lane & 3) * 2;
    #pragma unroll
    for (int mt = 0; mt < 4; ++mt) {
        #pragma unroll
        for (int nt = 0; nt < 4; ++nt) {
            int gm = m0 + wm*64 + mt*16 + cr;
            int gn = n0 + wn*32 + nt*8 + cc;
            float2 v0, v1;
            v0.x = mult*acc[mt][nt][0]; v0.y = mult*acc[mt][nt][1];
            v1.x = mult*acc[mt][nt][2]; v1.y = mult*acc[mt][nt][3];
            if (beta != 0.f) {
                float2 d0 = *(const float2*)&Dm[(size_t)gm*ldd + gn];
                float2 d1 = *(const float2*)&Dm[(size_t)(gm+8)*ldd + gn];
                v0.x += beta*d0.x; v0.y += beta*d0.y;
                v1.x += beta*d1.x; v1.y += beta*d1.y;
            }
            *(float2*)&C[(size_t)gm*ldc + gn] = v0;
            *(float2*)&C[(size_t)(gm+8)*ldc + gn] = v1;
        }
    }
}

// ---------------- scan: chunked recurrence with warmup ----------------
// grid = 148 (74 chunks x 2 batch-halves), block = 256 threads (2 state cols each)
__global__ __launch_bounds__(256)
void scan_kernel(const float* __restrict__ Bu, const float* __restrict__ Apack,
                 const float* __restrict__ state0, float* __restrict__ states)
{
    __shared__ float xs[8][DX];
    int tid = threadIdx.x;
    int n = tid * 2;
    int c = blockIdx.x >> 1, hb = blockIdx.x & 1, b0 = hb * 8;
    int t0 = c * CTS;
    int tend = t0 + CTS; if (tend > SEQL) tend = SEQL;
    int tstart = t0 - CW; if (tstart < 0) tstart = 0;
    bool fromstate = (tstart == 0);

    #pragma unroll
    for (int b = 0; b < 8; ++b) {
        float2 v = fromstate ? *(const float2*)(state0 + (size_t)(b0+b)*DX + n)
                             : make_float2(0.f, 0.f);
        *(float2*)&xs[b][n] = v;
    }
    __syncthreads();

    for (int t = tstart; t < tend; ++t) {
        float2 acc[8];
        #pragma unroll
        for (int b = 0; b < 8; ++b)
            acc[b] = *(const float2*)(Bu + ((size_t)(b0+b)*SEQL + t)*DX + n);
        #pragma unroll 4
        for (int h4 = 0; h4 < DX/4; ++h4) {
            const float* ap = Apack + (size_t)h4*(DX*4) + n*4;
            float4 a0 = *(const float4*)(ap);
            float4 a1 = *(const float4*)(ap + 4);
            #pragma unroll
            for (int b = 0; b < 8; ++b) {
                float4 xv = *(const float4*)(&xs[b][h4*4]);
                acc[b].x += a0.x*xv.x + a0.y*xv.y + a0.z*xv.z + a0.w*xv.w;
                acc[b].y += a1.x*xv.x + a1.y*xv.y + a1.z*xv.z + a1.w*xv.w;
            }
        }
        __syncthreads();
        bool wr = (t >= t0);
        #pragma unroll
        for (int b = 0; b < 8; ++b) {
            *(float2*)&xs[b][n] = acc[b];
            if (wr)
                *(float2*)(states + ((size_t)(b0+b)*(SEQL+1) + (t+1))*DX + n) = acc[b];
        }
        __syncthreads();
    }
}

// ---------------- host ----------------
static void* symaddr(const void* sym) {
    void* p = nullptr;
    cudaGetSymbolAddress(&p, sym);
    return p;
}

// bmode: 0 = A-operand layout [h,l,h], 1 = B-operand layout [h,h,l]
static void SPLIT(const float* src, __nv_bfloat16* dst, long long rs, long long cs,
                  int K, long long rows, int bmode, int rpb = 0, long long bstr = 0)
{
    long long total = rows * (long long)K;
    int grid = (int)((total + 255) / 256);
    split3_kernel<<<grid, 256>>>(src, dst, rs, cs, K, total, rpb, bstr, bmode);
}

static void TCG(const __nv_bfloat16* A3, const __nv_bfloat16* B3, const float* Dm, float* Cp,
                int M, int N, int K3, int ldd, int ldc, int amode, float alpha, float beta)
{
    dim3 g(N/128, M/128);
    tc_gemm<<<g, 256, 65536>>>(A3, B3, Dm, Cp, M, N, K3, ldd, ldc, amode, alpha, beta);
}

extern "C" void kernel_launch(void* const* d_in, const int* in_sizes, int n_in,
                              void* d_out, int out_size)
{
    const float *u = nullptr, *state = nullptr, *S = nullptr, *Kraw = nullptr;
    for (int i = 0; i < n_in; ++i) {
        long long sz = in_sizes[i];
        if      (sz == (long long)NB*SEQL*DU) u     = (const float*)d_in[i];
        else if (sz == (long long)NB*DX)      state = (const float*)d_in[i];
        else if (sz == (long long)DX*DX)      S     = (const float*)d_in[i];
        else if (sz == (long long)DK*DK)      Kraw  = (const float*)d_in[i];
    }
    float* out = (float*)d_out;

    cudaFuncSetAttribute(tc_gemm, cudaFuncAttributeMaxDynamicSharedMemorySize, 65536);

    float* pM0    = (float*)symaddr(g_M0);
    float* pM1    = (float*)symaddr(g_M1);
    float* pXa    = (float*)symaddr(g_Xa);
    float* pXb    = (float*)symaddr(g_Xb);
    float* pP     = (float*)symaddr(g_P);
    float* pT1    = (float*)symaddr(g_T1);
    float* pAmat  = (float*)symaddr(g_Amat);
    float* pApack = (float*)symaddr(g_Apack);
    float* pBm    = (float*)symaddr(g_Bm);
    float* pE     = (float*)symaddr(g_E);
    float* pBu    = (float*)symaddr(g_Bu);
    float* pFall  = (float*)symaddr(g_states_fallback);

    __nv_bfloat16* pcBig1 = (__nv_bfloat16*)symaddr(c_big1);
    __nv_bfloat16* pcBig2 = (__nv_bfloat16*)symaddr(c_big2);
    __nv_bfloat16* pcKT   = (__nv_bfloat16*)symaddr(c_kt);
    __nv_bfloat16* pcM    = (__nv_bfloat16*)symaddr(c_m);
    __nv_bfloat16* pcS    = (__nv_bfloat16*)symaddr(c_s);
    __nv_bfloat16* pcST   = (__nv_bfloat16*)symaddr(c_st);
    __nv_bfloat16* pcW1   = (__nv_bfloat16*)symaddr(c_w1);
    __nv_bfloat16* pcW2   = (__nv_bfloat16*)symaddr(c_w2);
    __nv_bfloat16* pcW3   = (__nv_bfloat16*)symaddr(c_w3);
    __nv_bfloat16* pcW4   = (__nv_bfloat16*)symaddr(c_w4);
    __nv_bfloat16* pcBm   = (__nv_bfloat16*)symaddr(c_bm);
    __nv_bfloat16* pcDw   = (__nv_bfloat16*)symaddr(c_dw);

    float* states = ((long long)out_size >= (long long)OUT_ELEMS + (long long)ST_ELEMS)
                    ? (out + OUT_ELEMS) : pFall;

    // --- init (logacc=0, X0=I) ---
    init_kernel<<<(DX*DX + 255)/256, 256>>>();

    // --- sigma: M0 = K^T K, then 10 trace-normalized squarings (TC) ---
    // A-operand: K^T rows (A-layout); B-operand: K^T rows (B-layout).
    SPLIT(Kraw, pcKT, 1, DK, DK, DK, 0);                    // K^T, A-side
    SPLIT(Kraw, pcM,  1, DK, DK, DK, 1);                    // K^T, B-side
    TCG(pcKT, pcM, nullptr, pM0, DK, DK, 3*DK, 0, DK, 0, 1.f, 0.f);
    float* Ms[2] = {pM0, pM1};
    double w = 1.0;
    for (int i = 0; i < 10; ++i) {
        trace_kernel<<<1,256>>>(Ms[i & 1], w);
        w *= 0.5;
        SPLIT(Ms[i & 1], pcKT, DK, 1, DK, DK, 0);           // M rows, A-side (M symmetric)
        SPLIT(Ms[i & 1], pcM,  DK, 1, DK, DK, 1);           // M rows, B-side
        TCG(pcKT, pcM, nullptr, Ms[(i+1) & 1], DK, DK, 3*DK, 0, DK, 1, 1.f, 0.f);
    }
    trace_kernel<<<1,256>>>(Ms[0], w);
    finalize_kernel<<<1,1>>>();

    // --- Sinv via Newton-Schulz: X <- 2X - X S X, 5 iters (TC) ---
    SPLIT(S, pcS, DX, 1, DX, DX, 0);                        // S rows, A-side (once)
    float* Xc = pXa; float* Xn = pXb;
    for (int it = 0; it < 5; ++it) {
        SPLIT(Xc, pcW1, DX, 1, DX, DX, 0);                  // Xc rows, A-side
        SPLIT(Xc, pcW2, 1, DX, DX, DX, 1);                  // Xc^T, B-side
        TCG(pcS, pcW2, nullptr, pP, DX, DX, 1536, 0, DX, 0, 1.f, 0.f);   // P = S@Xc
        SPLIT(pP, pcW3, 1, DX, DX, DX, 1);                  // P^T, B-side
        TCG(pcW1, pcW3, Xc, Xn, DX, DX, 1536, DX, DX, 0, -1.f, 2.f);     // Xn = 2Xc - Xc@P
        float* tmp = Xc; Xc = Xn; Xn = tmp;
    }
    // Xc == Sinv

    // --- assemble A, B, C, D (all carry kscale; GAMMA=1) ---
    SPLIT(Xc, pcW4, DX, 1, DX, DX, 0);                      // Sinv rows, A-side
    SPLIT(S, pcST, 1, DX, DX, DX, 1);                       // S^T, B-side
    SPLIT(Kraw, pcW1, DK, 1, DX, DX, 0);                    // K11 rows, A-side [512 x 512]
    TCG(pcW1, pcST, nullptr, pT1, DX, DX, 1536, 0, DX, 2, 1.f, 0.f);     // T1 = ks*K11@S
    SPLIT(pT1, pcW2, 1, DX, DX, DX, 1);                     // T1^T, B-side
    TCG(pcW4, pcW2, nullptr, pAmat, DX, DX, 1536, 0, DX, 0, 1.f, 0.f);   // A = Sinv@T1
    pack_kernel<<<(DX*DX)/256, 256>>>();
    SPLIT(Kraw + DX, pcW3, 1, DK, DX, DU, 1);               // K12^T, B-side [256 x 512]
    TCG(pcW4, pcW3, nullptr, pBm, DX, DU, 1536, 0, DU, 2, 1.f, 0.f);     // B = ks*Sinv@K12
    SPLIT(Kraw + (size_t)DX*DK, pcW1, DK, 1, DX, DOUT, 0);  // K21 rows, A-side [256 x 512]
    TCG(pcW1, pcST, nullptr, pE, DOUT, DX, 1536, 0, DK, 2, 1.f, 0.f);    // C = ks*K21@S
    dcopy_kernel<<<(DOUT*DU)/256, 256>>>(Kraw);             // D block of E

    // --- Bu = u @ B^T  [65536 x 512] (TC) ---
    SPLIT(pBm, pcBm, DU, 1, DU, DX, 1);                     // Bm rows, B-side [512 x 256]
    SPLIT(u, pcBig2, DU, 1, DU, (long long)NB*SEQL, 0);     // u3, A-side [65536 x 768]
    TCG(pcBig2, pcBm, nullptr, pBu, NB*SEQL, DX, 768, 0, DX, 0, 1.f, 0.f);

    // --- scan ---
    state0_kernel<<<(NB*DX)/256, 256>>>(state, states);
    scan_kernel<<<2*NCH, 256>>>(pBu, pApack, state, states);

    // --- output = pre_states @ C^T + u @ D^T (TC) ---
    SPLIT(pE, pcW2, DK, 1, DX, DOUT, 1);                    // Cw rows, B-side [256 x 512]
    SPLIT(pE + DX, pcDw, DK, 1, DU, DOUT, 1);               // Dw rows, B-side [256 x 256]
    SPLIT(states, pcBig1, DX, 1, DX, (long long)NB*SEQL, 0, SEQL, (long long)(SEQL+1)*DX);
    TCG(pcBig1, pcW2, nullptr, out, NB*SEQL, DOUT, 1536, 0, DOUT, 0, 1.f, 0.f);
    TCG(pcBig2, pcDw, out, out, NB*SEQL, DOUT, 768, DOUT, DOUT, 0, 1.f, 1.f);
}

// round 10
// speedup vs baseline: 2.0990x; 2.0990x over previous
#include <cuda_runtime.h>
#include <cuda_bf16.h>
#include <cuda_fp16.h>
#include <math.h>
#include <stdint.h>

#define DX 512
#define DU 256
#define DOUT 256
#define DK 768
#define NB 16
#define SEQL 4096
#define CW 64          // warmup length
#define NCH 74         // chunks
#define CTS 56         // chunk length (74*56 = 4144 >= 4096)
#define OUT_ELEMS (NB*SEQL*DOUT)           /* 16777216 */
#define ST_ELEMS  ((size_t)NB*(SEQL+1)*DX) /* 33562624 */

// ---------------- device scratch (static; no runtime allocation) ----------------
__device__ float g_M0[DK*DK];
__device__ float g_M1[DK*DK];
__device__ float g_Xa[DX*DX];
__device__ float g_Xb[DX*DX];
__device__ float g_P[DX*DX];
__device__ float g_T1[DX*DX];
__device__ float g_Amat[DX*DX];
__device__ __half g_ApackH[DX*DX];
__device__ float g_Bm[DX*DU];
__device__ float g_E[DOUT*DK];
__device__ float g_Bu[(size_t)NB*SEQL*DX];
__device__ float g_states_fallback[(size_t)NB*(SEQL+1)*DX];
__device__ float g_part[64];
__device__ float g_scale;
__device__ float g_kscale;
__device__ double g_logacc;

// bf16 split buffers. A-side layout [h,l,h]; B-side layout [h,h,l].
__device__ __nv_bfloat16 c_big1[(size_t)65536*1536]; // states3 (A-side)
__device__ __nv_bfloat16 c_big2[(size_t)65536*768];  // u3 (A-side)
__device__ __nv_bfloat16 c_kt[DK*2304];              // A-side DK
__device__ __nv_bfloat16 c_m [DK*2304];              // B-side DK
__device__ __nv_bfloat16 c_s [DX*1536];
__device__ __nv_bfloat16 c_st[DX*1536];
__device__ __nv_bfloat16 c_w1[DX*1536];
__device__ __nv_bfloat16 c_w2[DX*1536];
__device__ __nv_bfloat16 c_w3[DX*1536];
__device__ __nv_bfloat16 c_w4[DX*1536];
__device__ __nv_bfloat16 c_bm[DX*768];
__device__ __nv_bfloat16 c_dw[DOUT*768];

// ---------------- small kernels ----------------
__global__ void init_kernel() {
    int idx = blockIdx.x * blockDim.x + threadIdx.x;
    if (idx == 0) g_logacc = 0.0;
    if (idx < DX*DX) {
        int i = idx / DX, j = idx - i*DX;
        g_Xa[idx] = (i == j) ? 1.f : 0.f;
    }
}

__global__ void trace_kernel(const float* __restrict__ M, double w) {
    __shared__ float red[256];
    int tid = threadIdx.x;
    float s = 0.f;
    for (int i = tid; i < DK; i += 256) s += M[(size_t)i*DK + i];
    red[tid] = s; __syncthreads();
    for (int o = 128; o > 0; o >>= 1) {
        if (tid < o) red[tid] += red[tid+o];
        __syncthreads();
    }
    if (tid == 0) {
        float t = red[0];
        g_scale = 1.f / (t * t);
        g_logacc += w * log((double)t);
    }
}

// Frobenius: tr(M^2) = ||M||_F^2 — stage 1: 64 partial sums
__global__ void frob_part(const float* __restrict__ M) {
    __shared__ float red[256];
    int tid = threadIdx.x;
    float s = 0.f;
    for (int i = blockIdx.x*256 + tid; i < DK*DK; i += 64*256) {
        float v = M[i]; s += v*v;
    }
    red[tid] = s; __syncthreads();
    for (int o = 128; o > 0; o >>= 1) {
        if (tid < o) red[tid] += red[tid+o];
        __syncthreads();
    }
    if (tid == 0) g_part[blockIdx.x] = red[0];
}

__global__ void frob_final(double w) {
    if (threadIdx.x == 0) {
        float t = 0.f;
        for (int i = 0; i < 64; ++i) t += g_part[i];
        g_logacc += w * log((double)t);
    }
}

__global__ void finalize_kernel() {
    double L = g_logacc;               // log(sigma^2)
    float sigma = (float)exp(0.5 * L);
    if (sigma < 1e-5f) sigma = 1e-5f;
    g_kscale = 1.f / (sigma + 0.002f);
}

// pack A (fp32) -> fp16 in scan layout: ApackH[(h4*256 + t)*8 + jj],
// n = 2t + (jj>>2), j = jj&3, value = A[n][h4*4 + j]
__global__ void pack_half_kernel() {
    int idx = blockIdx.x * blockDim.x + threadIdx.x;   // DX*DX
    int h4 = idx >> 11, t = (idx >> 3) & 255, jj = idx & 7;
    int n = 2*t + (jj >> 2), j = jj & 3;
    g_ApackH[idx] = __float2half(g_Amat[(size_t)n*DX + h4*4 + j]);
}

__global__ void dcopy_kernel(const float* __restrict__ Kraw) {
    int idx = blockIdx.x * blockDim.x + threadIdx.x;   // DOUT*DU
    int o = idx >> 8, h = idx & 255;
    g_E[(size_t)o*DK + DX + h] = g_kscale * Kraw[(size_t)(DX+o)*DK + DX + h];
}

__global__ void state0_kernel(const float* __restrict__ st, float* __restrict__ states) {
    int idx = blockIdx.x * blockDim.x + threadIdx.x;   // NB*DX
    int b = idx >> 9, n = idx & 511;
    states[(size_t)b*(SEQL+1)*DX + n] = st[idx];
}

// ---------------- fp32 -> bf16 3-term split, generic gather ----------------
// bmode=0 (A-operand): dst row = [hi | lo | hi]
// bmode=1 (B-operand): dst row = [hi | hi | lo]
// So A3 . B3 over K3 = Ah.Bh + Al.Bh + Ah.Bl  (lo*lo term dropped, ~2^-32)
__global__ void split3_kernel(const float* __restrict__ src, __nv_bfloat16* __restrict__ dst,
                              long long rs, long long cs, int K, long long total,
                              int rpb, long long bstr, int bmode)
{
    long long idx = (long long)blockIdx.x * 256 + threadIdx.x;
    if (idx >= total) return;
    long long r = idx / K;
    int k = (int)(idx - r * K);
    long long so;
    if (rpb > 0) { long long b = r / rpb, rr = r - b*rpb; so = b*bstr + rr*rs + (long long)k*cs; }
    else so = r*rs + (long long)k*cs;
    float x = src[so];
    __nv_bfloat16 h = __float2bfloat16(x);
    __nv_bfloat16 l = __float2bfloat16(x - __bfloat162float(h));
    __nv_bfloat16* d = dst + r*(3LL*K);
    if (bmode) { d[k] = h; d[K+k] = h; d[2*K+k] = l; }
    else       { d[k] = h; d[K+k] = l; d[2*K+k] = h; }
}

// ---------------- tensor-core bf16-split GEMM (mma.sync, sm_80-era path) ----------------
// C[M,N] = mult * (A3[M,K3] @ B3[N,K3]^T) + beta * Dm
// Template: MT = warp m16-tiles (warp tile M = MT*16), WN = warps in N.
// Fixed: 2 warps in M, warp tile N = 32 (NT=4). BM = MT*32, BN = WN*32, THREADS = WN*64.
__device__ __forceinline__ void cpa16(uint32_t s, const void* g) {
    asm volatile("cp.async.cg.shared.global [%0], [%1], 16;" :: "r"(s), "l"(g));
}
__device__ __forceinline__ void ldm4(uint32_t* f, uint32_t addr) {
    asm volatile("ldmatrix.sync.aligned.m8n8.x4.shared.b16 {%0,%1,%2,%3}, [%4];"
                 : "=r"(f[0]), "=r"(f[1]), "=r"(f[2]), "=r"(f[3]) : "r"(addr));
}
__device__ __forceinline__ void mma16816(float* c, const uint32_t* a, uint32_t b0, uint32_t b1) {
    asm volatile("mma.sync.aligned.m16n8k16.row.col.f32.bf16.bf16.f32 "
                 "{%0,%1,%2,%3}, {%4,%5,%6,%7}, {%8,%9}, {%0,%1,%2,%3};"
                 : "+f"(c[0]), "+f"(c[1]), "+f"(c[2]), "+f"(c[3])
                 : "r"(a[0]), "r"(a[1]), "r"(a[2]), "r"(a[3]), "r"(b0), "r"(b1));
}
#define SWZ(x) ((x) ^ (((x) >> 3) & 0x70))

template<int MT, int WN>
__global__ __launch_bounds__(WN*64)
void tc_gemm(const __nv_bfloat16* __restrict__ A3, const __nv_bfloat16* __restrict__ B3,
             const float* __restrict__ Dm, float* __restrict__ C,
             int K3, int ldd, int ldc, int amode, float alpha, float beta)
{
    constexpr int BM = MT*32;
    constexpr int BN = WN*32;
    constexpr int THREADS = WN*64;
    constexpr uint32_t ABYTES = BM*128;
    constexpr uint32_t BBYTES = BN*128;
    constexpr uint32_t STAGE = ABYTES + BBYTES;

    extern __shared__ char smem[];
    uint32_t sbase = (uint32_t)__cvta_generic_to_shared(smem);

    int tid = threadIdx.x;
    int wid = tid >> 5, lane = tid & 31;
    int wm = wid & 1, wn = wid >> 1;
    int m0 = blockIdx.y * BM, n0 = blockIdx.x * BN;

    // ldmatrix per-lane addressing
    int q = lane >> 3, r = lane & 7;
    uint32_t aRow[MT], aXor[MT];
    #pragma unroll
    for (int mt = 0; mt < MT; ++mt) {
        int row = wm*(MT*16) + mt*16 + (q & 1)*8 + r;
        aRow[mt] = (uint32_t)row * 128;
        aXor[mt] = (uint32_t)(row & 7) * 16;
    }
    uint32_t aCsel = (uint32_t)(q >> 1) * 16;
    uint32_t bRow[2], bXor[2];
    #pragma unroll
    for (int p = 0; p < 2; ++p) {
        int row = wn*32 + (2*p + (q >> 1))*8 + r;
        bRow[p] = (uint32_t)row * 128;
        bXor[p] = (uint32_t)(row & 7) * 16;
    }
    uint32_t bCsel = (uint32_t)(q & 1) * 16;

    float acc[MT][4][4];
    #pragma unroll
    for (int i = 0; i < MT; ++i)
        #pragma unroll
        for (int j = 0; j < 4; ++j)
            #pragma unroll
            for (int v = 0; v < 4; ++v) acc[i][j][v] = 0.f;

    int nk = K3 >> 6;

    auto load_tile = [&](int j, int stg) {
        int kt = j << 6;
        uint32_t sA = sbase + (uint32_t)stg*STAGE;
        uint32_t sB = sA + ABYTES;
        #pragma unroll
        for (int i = 0; i < (BM*8)/THREADS; ++i) {
            int c = tid + i*THREADS;
            int row = c >> 3, col16 = c & 7;
            uint32_t off = (uint32_t)(row*128 + col16*16);
            cpa16(sA + SWZ(off), A3 + (size_t)(m0+row)*K3 + kt + col16*8);
        }
        #pragma unroll
        for (int i = 0; i < (BN*8)/THREADS; ++i) {
            int c = tid + i*THREADS;
            int row = c >> 3, col16 = c & 7;
            uint32_t off = (uint32_t)(row*128 + col16*16);
            cpa16(sB + SWZ(off), B3 + (size_t)(n0+row)*K3 + kt + col16*8);
        }
        asm volatile("cp.async.commit_group;" ::: "memory");
    };

    load_tile(0, 0);

    for (int ki = 0; ki < nk; ++ki) {
        int stg = ki & 1;
        if (ki + 1 < nk) {
            load_tile(ki + 1, stg ^ 1);
            asm volatile("cp.async.wait_group 1;" ::: "memory");
        } else {
            asm volatile("cp.async.wait_group 0;" ::: "memory");
        }
        __syncthreads();

        uint32_t sA = sbase + (uint32_t)stg*STAGE;
        uint32_t sB = sA + ABYTES;
        #pragma unroll
        for (int kk = 0; kk < 4; ++kk) {
            uint32_t afr[MT][4];
            #pragma unroll
            for (int mt = 0; mt < MT; ++mt)
                ldm4(afr[mt], sA + aRow[mt] + (((uint32_t)(kk*32) + aCsel) ^ aXor[mt]));
            uint32_t bfr[2][4];
            #pragma unroll
            for (int p = 0; p < 2; ++p)
                ldm4(bfr[p], sB + bRow[p] + (((uint32_t)(kk*32) + bCsel) ^ bXor[p]));
            #pragma unroll
            for (int mt = 0; mt < MT; ++mt)
                #pragma unroll
                for (int nt = 0; nt < 4; ++nt)
                    mma16816(acc[mt][nt], afr[mt], bfr[nt >> 1][(nt & 1)*2], bfr[nt >> 1][(nt & 1)*2 + 1]);
        }
        __syncthreads();
    }

    float mult = alpha;
    if (amode == 1) mult *= g_scale;
    else if (amode == 2) mult *= g_kscale;

    int cr = lane >> 2, cc = (lane & 3) * 2;
    #pragma unroll
    for (int mt = 0; mt < MT; ++mt) {
        #pragma unroll
        for (int nt = 0; nt < 4; ++nt) {
            int gm = m0 + wm*(MT*16) + mt*16 + cr;
            int gn = n0 + wn*32 + nt*8 + cc;
            float2 v0, v1;
            v0.x = mult*acc[mt][nt][0]; v0.y = mult*acc[mt][nt][1];
            v1.x = mult*acc[mt][nt][2]; v1.y = mult*acc[mt][nt][3];
            if (beta != 0.f) {
                float2 d0 = *(const float2*)&Dm[(size_t)gm*ldd + gn];
                float2 d1 = *(const float2*)&Dm[(size_t)(gm+8)*ldd + gn];
                v0.x += beta*d0.x; v0.y += beta*d0.y;
                v1.x += beta*d1.x; v1.y += beta*d1.y;
            }
            *(float2*)&C[(size_t)gm*ldc + gn] = v0;
            *(float2*)&C[(size_t)(gm+8)*ldc + gn] = v1;
        }
    }
}

// ---------------- scan: chunked recurrence with warmup, fp16 A ----------------
// grid = 148 (74 chunks x 2 batch-halves), block = 256 threads (2 state cols each)
__global__ __launch_bounds__(256)
void scan_kernel(const float* __restrict__ Bu, const __half* __restrict__ ApackH,
                 const float* __restrict__ state0, float* __restrict__ states)
{
    __shared__ float xs[8][DX];
    int tid = threadIdx.x;
    int n = tid * 2;
    int c = blockIdx.x >> 1, hb = blockIdx.x & 1, b0 = hb * 8;
    int t0 = c * CTS;
    int tend = t0 + CTS; if (tend > SEQL) tend = SEQL;
    int tstart = t0 - CW; if (tstart < 0) tstart = 0;
    bool fromstate = (tstart == 0);

    #pragma unroll
    for (int b = 0; b < 8; ++b) {
        float2 v = fromstate ? *(const float2*)(state0 + (size_t)(b0+b)*DX + n)
                             : make_float2(0.f, 0.f);
        *(float2*)&xs[b][n] = v;
    }
    __syncthreads();

    for (int t = tstart; t < tend; ++t) {
        float2 acc[8];
        #pragma unroll
        for (int b = 0; b < 8; ++b)
            acc[b] = *(const float2*)(Bu + ((size_t)(b0+b)*SEQL + t)*DX + n);
        #pragma unroll 4
        for (int h4 = 0; h4 < DX/4; ++h4) {
            uint4 av = *(const uint4*)(ApackH + (((size_t)h4*256 + tid) << 3));
            const __half2* hp = (const __half2*)&av;
            float2 f0 = __half22float2(hp[0]);
            float2 f1 = __half22float2(hp[1]);
            float2 f2 = __half22float2(hp[2]);
            float2 f3 = __half22float2(hp[3]);
            #pragma unroll
            for (int b = 0; b < 8; ++b) {
                float4 xv = *(const float4*)(&xs[b][h4*4]);
                acc[b].x += f0.x*xv.x + f0.y*xv.y + f1.x*xv.z + f1.y*xv.w;
                acc[b].y += f2.x*xv.x + f2.y*xv.y + f3.x*xv.z + f3.y*xv.w;
            }
        }
        __syncthreads();
        bool wr = (t >= t0);
        #pragma unroll
        for (int b = 0; b < 8; ++b) {
            *(float2*)&xs[b][n] = acc[b];
            if (wr)
                *(float2*)(states + ((size_t)(b0+b)*(SEQL+1) + (t+1))*DX + n) = acc[b];
        }
        __syncthreads();
    }
}

// ---------------- host ----------------
static void* symaddr(const void* sym) {
    void* p = nullptr;
    cudaGetSymbolAddress(&p, sym);
    return p;
}

// bmode: 0 = A-operand layout [h,l,h], 1 = B-operand layout [h,h,l]
static void SPLIT(const float* src, __nv_bfloat16* dst, long long rs, long long cs,
                  int K, long long rows, int bmode, int rpb = 0, long long bstr = 0)
{
    long long total = rows * (long long)K;
    int grid = (int)((total + 255) / 256);
    split3_kernel<<<grid, 256>>>(src, dst, rs, cs, K, total, rpb, bstr, bmode);
}

static void TCG(const __nv_bfloat16* A3, const __nv_bfloat16* B3, const float* Dm, float* Cp,
                int M, int N, int K3, int ldd, int ldc, int amode, float alpha, float beta)
{
    if (M >= 1024) {
        dim3 g(N/128, M/128);
        tc_gemm<4,4><<<g, 256, 65536>>>(A3, B3, Dm, Cp, K3, ldd, ldc, amode, alpha, beta);
    } else {
        dim3 g(N/64, M/64);
        tc_gemm<2,2><<<g, 128, 32768>>>(A3, B3, Dm, Cp, K3, ldd, ldc, amode, alpha, beta);
    }
}

extern "C" void kernel_launch(void* const* d_in, const int* in_sizes, int n_in,
                              void* d_out, int out_size)
{
    const float *u = nullptr, *state = nullptr, *S = nullptr, *Kraw = nullptr;
    for (int i = 0; i < n_in; ++i) {
        long long sz = in_sizes[i];
        if      (sz == (long long)NB*SEQL*DU) u     = (const float*)d_in[i];
        else if (sz == (long long)NB*DX)      state = (const float*)d_in[i];
        else if (sz == (long long)DX*DX)      S     = (const float*)d_in[i];
        else if (sz == (long long)DK*DK)      Kraw  = (const float*)d_in[i];
    }
    float* out = (float*)d_out;

    cudaFuncSetAttribute((const void*)tc_gemm<4,4>, cudaFuncAttributeMaxDynamicSharedMemorySize, 65536);

    float* pM0    = (float*)symaddr(g_M0);
    float* pM1    = (float*)symaddr(g_M1);
    float* pXa    = (float*)symaddr(g_Xa);
    float* pXb    = (float*)symaddr(g_Xb);
    float* pP     = (float*)symaddr(g_P);
    float* pT1    = (float*)symaddr(g_T1);
    float* pAmat  = (float*)symaddr(g_Amat);
    float* pBm    = (float*)symaddr(g_Bm);
    float* pE     = (float*)symaddr(g_E);
    float* pBu    = (float*)symaddr(g_Bu);
    float* pFall  = (float*)symaddr(g_states_fallback);
    __half* pAp16 = (__half*)symaddr(g_ApackH);

    __nv_bfloat16* pcBig1 = (__nv_bfloat16*)symaddr(c_big1);
    __nv_bfloat16* pcBig2 = (__nv_bfloat16*)symaddr(c_big2);
    __nv_bfloat16* pcKT   = (__nv_bfloat16*)symaddr(c_kt);
    __nv_bfloat16* pcM    = (__nv_bfloat16*)symaddr(c_m);
    __nv_bfloat16* pcS    = (__nv_bfloat16*)symaddr(c_s);
    __nv_bfloat16* pcST   = (__nv_bfloat16*)symaddr(c_st);
    __nv_bfloat16* pcW1   = (__nv_bfloat16*)symaddr(c_w1);
    __nv_bfloat16* pcW2   = (__nv_bfloat16*)symaddr(c_w2);
    __nv_bfloat16* pcW3   = (__nv_bfloat16*)symaddr(c_w3);
    __nv_bfloat16* pcW4   = (__nv_bfloat16*)symaddr(c_w4);
    __nv_bfloat16* pcBm   = (__nv_bfloat16*)symaddr(c_bm);
    __nv_bfloat16* pcDw   = (__nv_bfloat16*)symaddr(c_dw);

    float* states = ((long long)out_size >= (long long)OUT_ELEMS + (long long)ST_ELEMS)
                    ? (out + OUT_ELEMS) : pFall;

    // --- init (logacc=0, X0=I) ---
    init_kernel<<<(DX*DX + 255)/256, 256>>>();

    // --- sigma: M0 = K^T K, 8 trace-normalized squarings, Frobenius finish ---
    // Estimator telescopes to (1/1024)*log tr((K^T K)^512): K-exponent 1024.
    SPLIT(Kraw, pcKT, 1, DK, DK, DK, 0);                    // K^T, A-side
    SPLIT(Kraw, pcM,  1, DK, DK, DK, 1);                    // K^T, B-side
    TCG(pcKT, pcM, nullptr, pM0, DK, DK, 3*DK, 0, DK, 0, 1.f, 0.f);
    float* Ms[2] = {pM0, pM1};
    double w = 1.0;
    for (int i = 0; i < 8; ++i) {
        trace_kernel<<<1,256>>>(Ms[i & 1], w);
        w *= 0.5;
        SPLIT(Ms[i & 1], pcKT, DK, 1, DK, DK, 0);           // M rows, A-side (M symmetric)
        SPLIT(Ms[i & 1], pcM,  DK, 1, DK, DK, 1);           // M rows, B-side
        TCG(pcKT, pcM, nullptr, Ms[(i+1) & 1], DK, DK, 3*DK, 0, DK, 1, 1.f, 0.f);
    }
    frob_part<<<64,256>>>(Ms[0]);                           // M_8 in buffer 0
    frob_final<<<1,32>>>(w * 0.5);                          // weight 2^-9
    finalize_kernel<<<1,1>>>();

    // --- Sinv via Newton-Schulz: X <- 2X - X S X, 4 iters ---
    SPLIT(S, pcS, DX, 1, DX, DX, 0);                        // S rows, A-side (once)
    float* Xc = pXa; float* Xn = pXb;
    for (int it = 0; it < 4; ++it) {
        SPLIT(Xc, pcW1, DX, 1, DX, DX, 0);                  // Xc rows, A-side
        SPLIT(Xc, pcW2, 1, DX, DX, DX, 1);                  // Xc^T, B-side
        TCG(pcS, pcW2, nullptr, pP, DX, DX, 1536, 0, DX, 0, 1.f, 0.f);   // P = S@Xc
        SPLIT(pP, pcW3, 1, DX, DX, DX, 1);                  // P^T, B-side
        TCG(pcW1, pcW3, Xc, Xn, DX, DX, 1536, DX, DX, 0, -1.f, 2.f);     // Xn = 2Xc - Xc@P
        float* tmp = Xc; Xc = Xn; Xn = tmp;
    }
    // Xc == Sinv

    // --- assemble A, B, C, D (all carry kscale; GAMMA=1) ---
    SPLIT(Xc, pcW4, DX, 1, DX, DX, 0);                      // Sinv rows, A-side
    SPLIT(S, pcST, 1, DX, DX, DX, 1);                       // S^T, B-side
    SPLIT(Kraw, pcW1, DK, 1, DX, DX, 0);                    // K11 rows, A-side [512 x 512]
    TCG(pcW1, pcST, nullptr, pT1, DX, DX, 1536, 0, DX, 2, 1.f, 0.f);     // T1 = ks*K11@S
    SPLIT(pT1, pcW2, 1, DX, DX, DX, 1);                     // T1^T, B-side
    TCG(pcW4, pcW2, nullptr, pAmat, DX, DX, 1536, 0, DX, 0, 1.f, 0.f);   // A = Sinv@T1
    pack_half_kernel<<<(DX*DX)/256, 256>>>();
    SPLIT(Kraw + DX, pcW3, 1, DK, DX, DU, 1);               // K12^T, B-side [256 x 512]
    TCG(pcW4, pcW3, nullptr, pBm, DX, DU, 1536, 0, DU, 2, 1.f, 0.f);     // B = ks*Sinv@K12
    SPLIT(Kraw + (size_t)DX*DK, pcW1, DK, 1, DX, DOUT, 0);  // K21 rows, A-side [256 x 512]
    TCG(pcW1, pcST, nullptr, pE, DOUT, DX, 1536, 0, DK, 2, 1.f, 0.f);    // C = ks*K21@S
    dcopy_kernel<<<(DOUT*DU)/256, 256>>>(Kraw);             // D block of E

    // --- Bu = u @ B^T  [65536 x 512] ---
    SPLIT(pBm, pcBm, DU, 1, DU, DX, 1);                     // Bm rows, B-side [512 x 256]
    SPLIT(u, pcBig2, DU, 1, DU, (long long)NB*SEQL, 0);     // u3, A-side [65536 x 768]
    TCG(pcBig2, pcBm, nullptr, pBu, NB*SEQL, DX, 768, 0, DX, 0, 1.f, 0.f);

    // --- scan ---
    state0_kernel<<<(NB*DX)/256, 256>>>(state, states);
    scan_kernel<<<2*NCH, 256>>>(pBu, pAp16, state, states);

    // --- output = pre_states @ C^T + u @ D^T ---
    SPLIT(pE, pcW2, DK, 1, DX, DOUT, 1);                    // Cw rows, B-side [256 x 512]
    SPLIT(pE + DX, pcDw, DK, 1, DU, DOUT, 1);               // Dw rows, B-side [256 x 256]
    SPLIT(states, pcBig1, DX, 1, DX, (long long)NB*SEQL, 0, SEQL, (long long)(SEQL+1)*DX);
    TCG(pcBig1, pcW2, nullptr, out, NB*SEQL, DOUT, 1536, 0, DOUT, 0, 1.f, 0.f);
    TCG(pcBig2, pcDw, out, out, NB*SEQL, DOUT, 768, DOUT, DOUT, 0, 1.f, 1.f);
}

// round 11
// speedup vs baseline: 3.4196x; 1.6292x over previous
#include <cuda_runtime.h>
#include <cuda_bf16.h>
#include <cuda_fp16.h>
#include <math.h>
#include <stdint.h>

#define DX 512
#define DU 256
#define DOUT 256
#define DK 768
#define NB 16
#define SEQL 4096
#define CW 64           // warmup length
#define SCN_NCH 147     // chunks (147*28 = 4116 >= 4096)
#define SCN_CTS 28      // chunk length
#define OUT_ELEMS (NB*SEQL*DOUT)           /* 16777216 */
#define ST_ELEMS  ((size_t)NB*(SEQL+1)*DX) /* 33562624 */

// ---------------- device scratch (static; no runtime allocation) ----------------
__device__ float g_M0[DK*DK];
__device__ float g_M1[DK*DK];
__device__ float g_Xa[DX*DX];
__device__ float g_Xb[DX*DX];
__device__ float g_P[DX*DX];
__device__ float g_T1[DX*DX];
__device__ float g_Amat[DX*DX];
__device__ __half g_Apk[DX*DX];      // A in mma B-fragment layout, fp16
__device__ float g_Bm[DX*DU];
__device__ float g_E[DOUT*DK];
__device__ float g_Bu[(size_t)NB*SEQL*DX];
__device__ float g_states_fallback[(size_t)NB*(SEQL+1)*DX];
__device__ float g_part[64];
__device__ float g_scale;
__device__ float g_kscale;
__device__ double g_logacc;

// bf16 split buffers. A-side layout [h,l,h]; B-side layout [h,h,l].
__device__ __nv_bfloat16 c_big1[(size_t)65536*1536]; // states3 (A-side)
__device__ __nv_bfloat16 c_big2[(size_t)65536*768];  // u3 (A-side)
__device__ __nv_bfloat16 c_kt[DK*2304];              // A-side DK
__device__ __nv_bfloat16 c_m [DK*2304];              // B-side DK
__device__ __nv_bfloat16 c_s [DX*1536];
__device__ __nv_bfloat16 c_st[DX*1536];
__device__ __nv_bfloat16 c_w1[DX*1536];
__device__ __nv_bfloat16 c_w2[DX*1536];
__device__ __nv_bfloat16 c_w3[DX*1536];
__device__ __nv_bfloat16 c_w4[DX*1536];
__device__ __nv_bfloat16 c_bm[DX*768];
__device__ __nv_bfloat16 c_dw[DOUT*768];

// ---------------- small kernels ----------------
__global__ void init_kernel() {
    int idx = blockIdx.x * blockDim.x + threadIdx.x;
    if (idx == 0) g_logacc = 0.0;
    if (idx < DX*DX) {
        int i = idx / DX, j = idx - i*DX;
        g_Xa[idx] = (i == j) ? 1.f : 0.f;
    }
}

__global__ void trace_kernel(const float* __restrict__ M, double w) {
    __shared__ float red[256];
    int tid = threadIdx.x;
    float s = 0.f;
    for (int i = tid; i < DK; i += 256) s += M[(size_t)i*DK + i];
    red[tid] = s; __syncthreads();
    for (int o = 128; o > 0; o >>= 1) {
        if (tid < o) red[tid] += red[tid+o];
        __syncthreads();
    }
    if (tid == 0) {
        float t = red[0];
        g_scale = 1.f / (t * t);
        g_logacc += w * log((double)t);
    }
}

// Frobenius: tr(M^2) = ||M||_F^2 — stage 1: 64 partial sums
__global__ void frob_part(const float* __restrict__ M) {
    __shared__ float red[256];
    int tid = threadIdx.x;
    float s = 0.f;
    for (int i = blockIdx.x*256 + tid; i < DK*DK; i += 64*256) {
        float v = M[i]; s += v*v;
    }
    red[tid] = s; __syncthreads();
    for (int o = 128; o > 0; o >>= 1) {
        if (tid < o) red[tid] += red[tid+o];
        __syncthreads();
    }
    if (tid == 0) g_part[blockIdx.x] = red[0];
}

__global__ void frob_final(double w) {
    if (threadIdx.x == 0) {
        float t = 0.f;
        for (int i = 0; i < 64; ++i) t += g_part[i];
        g_logacc += w * log((double)t);
    }
}

__global__ void finalize_kernel() {
    double L = g_logacc;               // log(sigma^2)
    float sigma = (float)exp(0.5 * L);
    if (sigma < 1e-5f) sigma = 1e-5f;
    g_kscale = 1.f / (sigma + 0.002f);
}

// pack A (fp32, row n x col h) -> fp16 fragments for mma m16n8k16 B operand.
// Apk[(((nt*16 + ktp)*32 + lane)*8) + t*4 + j]:
//   tig = lane&3, gid = lane>>2, k = tig*2 + (j&1) + (j>>1)*8,
//   h = (2*ktp + t)*16 + k, n = nt*8 + gid, val = A[n][h]
__global__ void pack_frag_kernel() {
    int idx = blockIdx.x * blockDim.x + threadIdx.x;   // 262144
    int i = idx & 7, lane = (idx >> 3) & 31, ktp = (idx >> 8) & 15, nt = idx >> 12;
    int t = i >> 2, j = i & 3;
    int tig = lane & 3, gid = lane >> 2;
    int k = tig*2 + (j & 1) + ((j >> 1) * 8);
    int h = (2*ktp + t)*16 + k;
    int n = nt*8 + gid;
    g_Apk[idx] = __float2half(g_Amat[(size_t)n*DX + h]);
}

__global__ void dcopy_kernel(const float* __restrict__ Kraw) {
    int idx = blockIdx.x * blockDim.x + threadIdx.x;   // DOUT*DU
    int o = idx >> 8, h = idx & 255;
    g_E[(size_t)o*DK + DX + h] = g_kscale * Kraw[(size_t)(DX+o)*DK + DX + h];
}

__global__ void state0_kernel(const float* __restrict__ st, float* __restrict__ states) {
    int idx = blockIdx.x * blockDim.x + threadIdx.x;   // NB*DX
    int b = idx >> 9, n = idx & 511;
    states[(size_t)b*(SEQL+1)*DX + n] = st[idx];
}

// ---------------- fp32 -> bf16 3-term split, generic gather ----------------
__global__ void split3_kernel(const float* __restrict__ src, __nv_bfloat16* __restrict__ dst,
                              long long rs, long long cs, int K, long long total,
                              int rpb, long long bstr, int bmode)
{
    long long idx = (long long)blockIdx.x * 256 + threadIdx.x;
    if (idx >= total) return;
    long long r = idx / K;
    int k = (int)(idx - r * K);
    long long so;
    if (rpb > 0) { long long b = r / rpb, rr = r - b*rpb; so = b*bstr + rr*rs + (long long)k*cs; }
    else so = r*rs + (long long)k*cs;
    float x = src[so];
    __nv_bfloat16 h = __float2bfloat16(x);
    __nv_bfloat16 l = __float2bfloat16(x - __bfloat162float(h));
    __nv_bfloat16* d = dst + r*(3LL*K);
    if (bmode) { d[k] = h; d[K+k] = h; d[2*K+k] = l; }
    else       { d[k] = h; d[K+k] = l; d[2*K+k] = h; }
}

// dual: same gather, writes A-side AND B-side layouts in one pass
__global__ void split3_dual_kernel(const float* __restrict__ src,
                                   __nv_bfloat16* __restrict__ dstA,
                                   __nv_bfloat16* __restrict__ dstB,
                                   long long rs, long long cs, int K, long long total)
{
    long long idx = (long long)blockIdx.x * 256 + threadIdx.x;
    if (idx >= total) return;
    long long r = idx / K;
    int k = (int)(idx - r * K);
    float x = src[r*rs + (long long)k*cs];
    __nv_bfloat16 h = __float2bfloat16(x);
    __nv_bfloat16 l = __float2bfloat16(x - __bfloat162float(h));
    __nv_bfloat16* dA = dstA + r*(3LL*K);
    __nv_bfloat16* dB = dstB + r*(3LL*K);
    dA[k] = h; dA[K+k] = l; dA[2*K+k] = h;
    dB[k] = h; dB[K+k] = h; dB[2*K+k] = l;
}

// ---------------- tensor-core bf16-split GEMM (mma.sync) ----------------
__device__ __forceinline__ void cpa16(uint32_t s, const void* g) {
    asm volatile("cp.async.cg.shared.global [%0], [%1], 16;" :: "r"(s), "l"(g));
}
__device__ __forceinline__ void ldm4(uint32_t* f, uint32_t addr) {
    asm volatile("ldmatrix.sync.aligned.m8n8.x4.shared.b16 {%0,%1,%2,%3}, [%4];"
                 : "=r"(f[0]), "=r"(f[1]), "=r"(f[2]), "=r"(f[3]) : "r"(addr));
}
__device__ __forceinline__ void mma16816(float* c, const uint32_t* a, uint32_t b0, uint32_t b1) {
    asm volatile("mma.sync.aligned.m16n8k16.row.col.f32.bf16.bf16.f32 "
                 "{%0,%1,%2,%3}, {%4,%5,%6,%7}, {%8,%9}, {%0,%1,%2,%3};"
                 : "+f"(c[0]), "+f"(c[1]), "+f"(c[2]), "+f"(c[3])
                 : "r"(a[0]), "r"(a[1]), "r"(a[2]), "r"(a[3]), "r"(b0), "r"(b1));
}
__device__ __forceinline__ void mmaf16(float* c, const uint32_t* a, uint32_t b0, uint32_t b1) {
    asm volatile("mma.sync.aligned.m16n8k16.row.col.f32.f16.f16.f32 "
                 "{%0,%1,%2,%3}, {%4,%5,%6,%7}, {%8,%9}, {%0,%1,%2,%3};"
                 : "+f"(c[0]), "+f"(c[1]), "+f"(c[2]), "+f"(c[3])
                 : "r"(a[0]), "r"(a[1]), "r"(a[2]), "r"(a[3]), "r"(b0), "r"(b1));
}
#define SWZ(x) ((x) ^ (((x) >> 3) & 0x70))

template<int MT, int WN>
__global__ __launch_bounds__(WN*64)
void tc_gemm(const __nv_bfloat16* __restrict__ A3, const __nv_bfloat16* __restrict__ B3,
             const float* __restrict__ Dm, float* __restrict__ C,
             int K3, int ldd, int ldc, int amode, float alpha, float beta)
{
    constexpr int BM = MT*32;
    constexpr int BN = WN*32;
    constexpr int THREADS = WN*64;
    constexpr uint32_t ABYTES = BM*128;
    constexpr uint32_t BBYTES = BN*128;
    constexpr uint32_t STAGE = ABYTES + BBYTES;

    extern __shared__ char smem[];
    uint32_t sbase = (uint32_t)__cvta_generic_to_shared(smem);

    int tid = threadIdx.x;
    int wid = tid >> 5, lane = tid & 31;
    int wm = wid & 1, wn = wid >> 1;
    int m0 = blockIdx.y * BM, n0 = blockIdx.x * BN;

    int q = lane >> 3, r = lane & 7;
    uint32_t aRow[MT], aXor[MT];
    #pragma unroll
    for (int mt = 0; mt < MT; ++mt) {
        int row = wm*(MT*16) + mt*16 + (q & 1)*8 + r;
        aRow[mt] = (uint32_t)row * 128;
        aXor[mt] = (uint32_t)(row & 7) * 16;
    }
    uint32_t aCsel = (uint32_t)(q >> 1) * 16;
    uint32_t bRow[2], bXor[2];
    #pragma unroll
    for (int p = 0; p < 2; ++p) {
        int row = wn*32 + (2*p + (q >> 1))*8 + r;
        bRow[p] = (uint32_t)row * 128;
        bXor[p] = (uint32_t)(row & 7) * 16;
    }
    uint32_t bCsel = (uint32_t)(q & 1) * 16;

    float acc[MT][4][4];
    #pragma unroll
    for (int i = 0; i < MT; ++i)
        #pragma unroll
        for (int j = 0; j < 4; ++j)
            #pragma unroll
            for (int v = 0; v < 4; ++v) acc[i][j][v] = 0.f;

    int nk = K3 >> 6;

    auto load_tile = [&](int j, int stg) {
        int kt = j << 6;
        uint32_t sA = sbase + (uint32_t)stg*STAGE;
        uint32_t sB = sA + ABYTES;
        #pragma unroll
        for (int i = 0; i < (BM*8)/THREADS; ++i) {
            int c = tid + i*THREADS;
            int row = c >> 3, col16 = c & 7;
            uint32_t off = (uint32_t)(row*128 + col16*16);
            cpa16(sA + SWZ(off), A3 + (size_t)(m0+row)*K3 + kt + col16*8);
        }
        #pragma unroll
        for (int i = 0; i < (BN*8)/THREADS; ++i) {
            int c = tid + i*THREADS;
            int row = c >> 3, col16 = c & 7;
            uint32_t off = (uint32_t)(row*128 + col16*16);
            cpa16(sB + SWZ(off), B3 + (size_t)(n0+row)*K3 + kt + col16*8);
        }
        asm volatile("cp.async.commit_group;" ::: "memory");
    };

    load_tile(0, 0);

    for (int ki = 0; ki < nk; ++ki) {
        int stg = ki & 1;
        if (ki + 1 < nk) {
            load_tile(ki + 1, stg ^ 1);
            asm volatile("cp.async.wait_group 1;" ::: "memory");
        } else {
            asm volatile("cp.async.wait_group 0;" ::: "memory");
        }
        __syncthreads();

        uint32_t sA = sbase + (uint32_t)stg*STAGE;
        uint32_t sB = sA + ABYTES;
        #pragma unroll
        for (int kk = 0; kk < 4; ++kk) {
            uint32_t afr[MT][4];
            #pragma unroll
            for (int mt = 0; mt < MT; ++mt)
                ldm4(afr[mt], sA + aRow[mt] + (((uint32_t)(kk*32) + aCsel) ^ aXor[mt]));
            uint32_t bfr[2][4];
            #pragma unroll
            for (int p = 0; p < 2; ++p)
                ldm4(bfr[p], sB + bRow[p] + (((uint32_t)(kk*32) + bCsel) ^ bXor[p]));
            #pragma unroll
            for (int mt = 0; mt < MT; ++mt)
                #pragma unroll
                for (int nt = 0; nt < 4; ++nt)
                    mma16816(acc[mt][nt], afr[mt], bfr[nt >> 1][(nt & 1)*2], bfr[nt >> 1][(nt & 1)*2 + 1]);
        }
        __syncthreads();
    }

    float mult = alpha;
    if (amode == 1) mult *= g_scale;
    else if (amode == 2) mult *= g_kscale;

    int cr = lane >> 2, cc = (lane & 3) * 2;
    #pragma unroll
    for (int mt = 0; mt < MT; ++mt) {
        #pragma unroll
        for (int nt = 0; nt < 4; ++nt) {
            int gm = m0 + wm*(MT*16) + mt*16 + cr;
            int gn = n0 + wn*32 + nt*8 + cc;
            float2 v0, v1;
            v0.x = mult*acc[mt][nt][0]; v0.y = mult*acc[mt][nt][1];
            v1.x = mult*acc[mt][nt][2]; v1.y = mult*acc[mt][nt][3];
            if (beta != 0.f) {
                float2 d0 = *(const float2*)&Dm[(size_t)gm*ldd + gn];
                float2 d1 = *(const float2*)&Dm[(size_t)(gm+8)*ldd + gn];
                v0.x += beta*d0.x; v0.y += beta*d0.y;
                v1.x += beta*d1.x; v1.y += beta*d1.y;
            }
            *(float2*)&C[(size_t)gm*ldc + gn] = v0;
            *(float2*)&C[(size_t)(gm+8)*ldc + gn] = v1;
        }
    }
}

// ---------------- scan via mma.sync fp16 ----------------
// grid = 147 CTAs (one chunk each, all 16 batches), 256 threads = 8 warps.
// Per step: x_new[16,512] = x[16,512] @ A^T + Bu[:,t,:]
//   A fp16 in fragment layout (gmem, L2-resident), x as (xh, xl) fp16 pair in
//   double-buffered smem (row pitch 1040 B -> conflict-free ldmatrix).
// Warp w owns output cols [w*64, w*64+64).
#define XPITCH_B 1040u            /* bytes per x row (512*2 + 16 pad) */
#define HLBYTES  (16u*XPITCH_B)   /* one h or l section: 16640 B */
#define BUFBYTES (2u*HLBYTES)     /* h + l: 33280 B */
#define SCN_SMEM (2u*BUFBYTES)    /* double buffer: 66560 B */

__global__ __launch_bounds__(256)
void scan_mma_kernel(const float* __restrict__ Bu, const __half* __restrict__ Apk,
                     const float* __restrict__ state0, float* __restrict__ states)
{
    extern __shared__ char sm[];
    uint32_t sbase = (uint32_t)__cvta_generic_to_shared(sm);
    int tid = threadIdx.x, wid = tid >> 5, lane = tid & 31;
    int gid = lane >> 2, tig = lane & 3;
    int q = lane >> 3, rr = lane & 7;
    uint32_t lrow = (uint32_t)((q & 1)*8 + rr) * XPITCH_B;
    uint32_t lcs  = (uint32_t)(q >> 1) * 16;

    int c = blockIdx.x;
    int t0 = c * SCN_CTS;
    int tend = t0 + SCN_CTS; if (tend > SEQL) tend = SEQL;
    int tstart = t0 - CW; if (tstart < 0) tstart = 0;
    bool fromstate = (tstart == 0);

    // init buffer 0 (h and l sections)
    for (int i = tid; i < 16*512; i += 256) {
        int m = i >> 9, n = i & 511;
        float v = fromstate ? state0[(size_t)m*DX + n] : 0.f;
        __half h = __float2half(v);
        __half l = __float2half(v - __half2float(h));
        *(__half*)(sm + m*XPITCH_B + n*2) = h;
        *(__half*)(sm + HLBYTES + m*XPITCH_B + n*2) = l;
    }
    __syncthreads();

    int nbase = wid * 64;
    int buf = 0;

    for (int t = tstart; t < tend; ++t) {
        // accumulators init from Bu
        float acc[8][4];
        {
            const float* bu0 = Bu + ((size_t)gid*SEQL + t)*DX;
            const float* bu1 = Bu + ((size_t)(gid+8)*SEQL + t)*DX;
            #pragma unroll
            for (int nt = 0; nt < 8; ++nt) {
                int n = nbase + nt*8 + tig*2;
                float2 v0 = *(const float2*)(bu0 + n);
                float2 v1 = *(const float2*)(bu1 + n);
                acc[nt][0] = v0.x; acc[nt][1] = v0.y;
                acc[nt][2] = v1.x; acc[nt][3] = v1.y;
            }
        }
        uint32_t bh = sbase + (uint32_t)buf*BUFBYTES;
        uint32_t bl = bh + HLBYTES;

        #pragma unroll 2
        for (int ktp = 0; ktp < 16; ++ktp) {
            uint32_t afh0[4], afh1[4], afl0[4], afl1[4];
            uint32_t cb = (uint32_t)(ktp*64);   // 2 k-tiles = 64 bytes
            ldm4(afh0, bh + lrow + cb + lcs);
            ldm4(afh1, bh + lrow + cb + 32 + lcs);
            ldm4(afl0, bl + lrow + cb + lcs);
            ldm4(afl1, bl + lrow + cb + 32 + lcs);
            #pragma unroll
            for (int nt = 0; nt < 8; ++nt) {
                uint4 bv = *(const uint4*)(Apk +
                    ((((size_t)(wid*8 + nt)*16 + ktp)*32 + lane) << 3));
                mmaf16(acc[nt], afh0, bv.x, bv.y);
                mmaf16(acc[nt], afh1, bv.z, bv.w);
                mmaf16(acc[nt], afl0, bv.x, bv.y);
                mmaf16(acc[nt], afl1, bv.z, bv.w);
            }
        }

        // epilogue: write x_new to other buffer (+ states if t >= t0)
        char* nb = sm + (buf ^ 1)*BUFBYTES;
        bool wr = (t >= t0);
        float* st0 = states + ((size_t)gid*(SEQL+1) + (t+1))*DX;
        float* st1 = states + ((size_t)(gid+8)*(SEQL+1) + (t+1))*DX;
        #pragma unroll
        for (int nt = 0; nt < 8; ++nt) {
            int n = nbase + nt*8 + tig*2;
            float v0 = acc[nt][0], v1 = acc[nt][1];
            float v2 = acc[nt][2], v3 = acc[nt][3];
            __half h0 = __float2half(v0), h1 = __float2half(v1);
            __half h2 = __float2half(v2), h3 = __float2half(v3);
            __half l0 = __float2half(v0 - __half2float(h0));
            __half l1 = __float2half(v1 - __half2float(h1));
            __half l2 = __float2half(v2 - __half2float(h2));
            __half l3 = __float2half(v3 - __half2float(h3));
            *(__half2*)(nb + gid*XPITCH_B + n*2)                    = __halves2half2(h0, h1);
            *(__half2*)(nb + (gid+8)*XPITCH_B + n*2)                = __halves2half2(h2, h3);
            *(__half2*)(nb + HLBYTES + gid*XPITCH_B + n*2)          = __halves2half2(l0, l1);
            *(__half2*)(nb + HLBYTES + (gid+8)*XPITCH_B + n*2)      = __halves2half2(l2, l3);
            if (wr) {
                *(float2*)(st0 + n) = make_float2(v0, v1);
                *(float2*)(st1 + n) = make_float2(v2, v3);
            }
        }
        __syncthreads();
        buf ^= 1;
    }
}

// ---------------- host ----------------
static void* symaddr(const void* sym) {
    void* p = nullptr;
    cudaGetSymbolAddress(&p, sym);
    return p;
}

static void SPLIT(const float* src, __nv_bfloat16* dst, long long rs, long long cs,
                  int K, long long rows, int bmode, int rpb = 0, long long bstr = 0)
{
    long long total = rows * (long long)K;
    int grid = (int)((total + 255) / 256);
    split3_kernel<<<grid, 256>>>(src, dst, rs, cs, K, total, rpb, bstr, bmode);
}

static void SPLITD(const float* src, __nv_bfloat16* dstA, __nv_bfloat16* dstB,
                   long long rs, long long cs, int K, long long rows)
{
    long long total = rows * (long long)K;
    int grid = (int)((total + 255) / 256);
    split3_dual_kernel<<<grid, 256>>>(src, dstA, dstB, rs, cs, K, total);
}

static void TCG(const __nv_bfloat16* A3, const __nv_bfloat16* B3, const float* Dm, float* Cp,
                int M, int N, int K3, int ldd, int ldc, int amode, float alpha, float beta)
{
    if (M >= 1024) {
        dim3 g(N/128, M/128);
        tc_gemm<4,4><<<g, 256, 65536>>>(A3, B3, Dm, Cp, K3, ldd, ldc, amode, alpha, beta);
    } else {
        dim3 g(N/64, M/64);
        tc_gemm<2,2><<<g, 128, 32768>>>(A3, B3, Dm, Cp, K3, ldd, ldc, amode, alpha, beta);
    }
}

extern "C" void kernel_launch(void* const* d_in, const int* in_sizes, int n_in,
                              void* d_out, int out_size)
{
    const float *u = nullptr, *state = nullptr, *S = nullptr, *Kraw = nullptr;
    for (int i = 0; i < n_in; ++i) {
        long long sz = in_sizes[i];
        if      (sz == (long long)NB*SEQL*DU) u     = (const float*)d_in[i];
        else if (sz == (long long)NB*DX)      state = (const float*)d_in[i];
        else if (sz == (long long)DX*DX)      S     = (const float*)d_in[i];
        else if (sz == (long long)DK*DK)      Kraw  = (const float*)d_in[i];
    }
    float* out = (float*)d_out;

    cudaFuncSetAttribute((const void*)tc_gemm<4,4>, cudaFuncAttributeMaxDynamicSharedMemorySize, 65536);
    cudaFuncSetAttribute((const void*)scan_mma_kernel, cudaFuncAttributeMaxDynamicSharedMemorySize, SCN_SMEM);

    float* pM0    = (float*)symaddr(g_M0);
    float* pM1    = (float*)symaddr(g_M1);
    float* pXa    = (float*)symaddr(g_Xa);
    float* pXb    = (float*)symaddr(g_Xb);
    float* pP     = (float*)symaddr(g_P);
    float* pT1    = (float*)symaddr(g_T1);
    float* pAmat  = (float*)symaddr(g_Amat);
    float* pBm    = (float*)symaddr(g_Bm);
    float* pE     = (float*)symaddr(g_E);
    float* pBu    = (float*)symaddr(g_Bu);
    float* pFall  = (float*)symaddr(g_states_fallback);
    __half* pApk  = (__half*)symaddr(g_Apk);

    __nv_bfloat16* pcBig1 = (__nv_bfloat16*)symaddr(c_big1);
    __nv_bfloat16* pcBig2 = (__nv_bfloat16*)symaddr(c_big2);
    __nv_bfloat16* pcKT   = (__nv_bfloat16*)symaddr(c_kt);
    __nv_bfloat16* pcM    = (__nv_bfloat16*)symaddr(c_m);
    __nv_bfloat16* pcS    = (__nv_bfloat16*)symaddr(c_s);
    __nv_bfloat16* pcST   = (__nv_bfloat16*)symaddr(c_st);
    __nv_bfloat16* pcW1   = (__nv_bfloat16*)symaddr(c_w1);
    __nv_bfloat16* pcW2   = (__nv_bfloat16*)symaddr(c_w2);
    __nv_bfloat16* pcW3   = (__nv_bfloat16*)symaddr(c_w3);
    __nv_bfloat16* pcW4   = (__nv_bfloat16*)symaddr(c_w4);
    __nv_bfloat16* pcBm   = (__nv_bfloat16*)symaddr(c_bm);
    __nv_bfloat16* pcDw   = (__nv_bfloat16*)symaddr(c_dw);

    float* states = ((long long)out_size >= (long long)OUT_ELEMS + (long long)ST_ELEMS)
                    ? (out + OUT_ELEMS) : pFall;

    // --- init (logacc=0, X0=I) ---
    init_kernel<<<(DX*DX + 255)/256, 256>>>();

    // --- sigma: M0 = K^T K, 8 trace-normalized squarings, Frobenius finish ---
    SPLITD(Kraw, pcKT, pcM, 1, DK, DK, DK);                 // K^T, both sides
    TCG(pcKT, pcM, nullptr, pM0, DK, DK, 3*DK, 0, DK, 0, 1.f, 0.f);
    float* Ms[2] = {pM0, pM1};
    double w = 1.0;
    for (int i = 0; i < 8; ++i) {
        trace_kernel<<<1,256>>>(Ms[i & 1], w);
        w *= 0.5;
        SPLITD(Ms[i & 1], pcKT, pcM, DK, 1, DK, DK);        // M rows, both sides
        TCG(pcKT, pcM, nullptr, Ms[(i+1) & 1], DK, DK, 3*DK, 0, DK, 1, 1.f, 0.f);
    }
    frob_part<<<64,256>>>(Ms[0]);                           // M_8 in buffer 0
    frob_final<<<1,32>>>(w * 0.5);                          // weight 2^-9
    finalize_kernel<<<1,1>>>();

    // --- Sinv via Newton-Schulz: X <- 2X - X S X, 4 iters ---
    SPLIT(S, pcS, DX, 1, DX, DX, 0);                        // S rows, A-side (once)
    float* Xc = pXa; float* Xn = pXb;
    for (int it = 0; it < 4; ++it) {
        SPLIT(Xc, pcW1, DX, 1, DX, DX, 0);                  // Xc rows, A-side
        SPLIT(Xc, pcW2, 1, DX, DX, DX, 1);                  // Xc^T, B-side
        TCG(pcS, pcW2, nullptr, pP, DX, DX, 1536, 0, DX, 0, 1.f, 0.f);   // P = S@Xc
        SPLIT(pP, pcW3, 1, DX, DX, DX, 1);                  // P^T, B-side
        TCG(pcW1, pcW3, Xc, Xn, DX, DX, 1536, DX, DX, 0, -1.f, 2.f);     // Xn = 2Xc - Xc@P
        float* tmp = Xc; Xc = Xn; Xn = tmp;
    }
    // Xc == Sinv

    // --- assemble A, B, C, D (all carry kscale; GAMMA=1) ---
    SPLIT(Xc, pcW4, DX, 1, DX, DX, 0);                      // Sinv rows, A-side
    SPLIT(S, pcST, 1, DX, DX, DX, 1);                       // S^T, B-side
    SPLIT(Kraw, pcW1, DK, 1, DX, DX, 0);                    // K11 rows, A-side [512 x 512]
    TCG(pcW1, pcST, nullptr, pT1, DX, DX, 1536, 0, DX, 2, 1.f, 0.f);     // T1 = ks*K11@S
    SPLIT(pT1, pcW2, 1, DX, DX, DX, 1);                     // T1^T, B-side
    TCG(pcW4, pcW2, nullptr, pAmat, DX, DX, 1536, 0, DX, 0, 1.f, 0.f);   // A = Sinv@T1
    pack_frag_kernel<<<(DX*DX)/256, 256>>>();
    SPLIT(Kraw + DX, pcW3, 1, DK, DX, DU, 1);               // K12^T, B-side [256 x 512]
    TCG(pcW4, pcW3, nullptr, pBm, DX, DU, 1536, 0, DU, 2, 1.f, 0.f);     // B = ks*Sinv@K12
    SPLIT(Kraw + (size_t)DX*DK, pcW1, DK, 1, DX, DOUT, 0);  // K21 rows, A-side [256 x 512]
    TCG(pcW1, pcST, nullptr, pE, DOUT, DX, 1536, 0, DK, 2, 1.f, 0.f);    // C = ks*K21@S
    dcopy_kernel<<<(DOUT*DU)/256, 256>>>(Kraw);             // D block of E

    // --- Bu = u @ B^T  [65536 x 512] ---
    SPLIT(pBm, pcBm, DU, 1, DU, DX, 1);                     // Bm rows, B-side [512 x 256]
    SPLIT(u, pcBig2, DU, 1, DU, (long long)NB*SEQL, 0);     // u3, A-side [65536 x 768]
    TCG(pcBig2, pcBm, nullptr, pBu, NB*SEQL, DX, 768, 0, DX, 0, 1.f, 0.f);

    // --- scan (mma.sync fp16, 147 chunk CTAs) ---
    state0_kernel<<<(NB*DX)/256, 256>>>(state, states);
    scan_mma_kernel<<<SCN_NCH, 256, SCN_SMEM>>>(pBu, pApk, state, states);

    // --- output = pre_states @ C^T + u @ D^T ---
    SPLIT(pE, pcW2, DK, 1, DX, DOUT, 1);                    // Cw rows, B-side [256 x 512]
    SPLIT(pE + DX, pcDw, DK, 1, DU, DOUT, 1);               // Dw rows, B-side [256 x 256]
    SPLIT(states, pcBig1, DX, 1, DX, (long long)NB*SEQL, 0, SEQL, (long long)(SEQL+1)*DX);
    TCG(pcBig1, pcW2, nullptr, out, NB*SEQL, DOUT, 1536, 0, DOUT, 0, 1.f, 0.f);
    TCG(pcBig2, pcDw, out, out, NB*SEQL, DOUT, 768, DOUT, DOUT, 0, 1.f, 1.f);
}